// round 2
// baseline (speedup 1.0000x reference)
#include <cuda_runtime.h>
#include <math.h>

// Problem constants (fixed by the benchmark shapes)
#define BHX   32          // b*h = 4*8
#define SEQ   4096        // n
#define DDIM  64          // d (= e)
#define MDIM  266         // m = number of random features
#define NCH   5           // ceil(M/64) column chunks
#define CTXW  65          // context width: 64 v-cols + 1 kmean col
#define EPSF  1e-4f
#define DNORM 0.35355339059327373f   // 64^-0.25

// -------- persistent scratch (device globals: allocation-free) --------
__device__ float        g_dash[(size_t)BHX * SEQ * MDIM]; // kd then qd (139.5 MB)
__device__ float        g_diag[BHX * SEQ];
__device__ float        g_rowmax[BHX * SEQ];
__device__ float        g_ctx[BHX * MDIM * CTXW];         // [bh][j][e + kmean]
__device__ unsigned int g_kstab_bits;

// monotonic float <-> uint mapping for deterministic atomicMax on floats
__device__ __forceinline__ unsigned int enc_f(float f) {
    int i = __float_as_int(f);
    return (i >= 0) ? ((unsigned int)i | 0x80000000u) : (unsigned int)(~i);
}
__device__ __forceinline__ float dec_f(unsigned int u) {
    int i = (u & 0x80000000u) ? (int)(u & 0x7fffffffu) : (~(int)u);
    return __int_as_float(i);
}

__global__ void reset_kernel() {
    g_kstab_bits = 0x007FFFFFu;   // enc(-inf)
}

// ---------------------------------------------------------------------
// dash = (DNORM * A) @ P^T    A:[bh][SEQ][64]  P:[266][64]
// also: g_diag (0.5*sum(scaled^2)); row-max (query) or global max (key)
// block: 64 rows of one bh; 256 threads; 4x4 micro-tile
// ---------------------------------------------------------------------
template<bool IS_QUERY>
__global__ void __launch_bounds__(256) dash_kernel(const float* __restrict__ A,
                                                   const float* __restrict__ P)
{
    const int bh  = blockIdx.y;
    const int r0  = blockIdx.x * 64;
    const int tid = threadIdx.x;
    const int tx  = tid & 15, ty = tid >> 4;

    __shared__ __align__(16) float sAT[DDIM][68];  // [k][row]  (transposed)
    __shared__ __align__(16) float sPT[DDIM][68];  // [k][jrel] (transposed)
    __shared__ float sRM[64][17];

    // vectorized fill: 64 rows x 64 cols = 4096 floats = 1024 float4
    const float4* Ab4 = reinterpret_cast<const float4*>(
        A + ((size_t)bh * SEQ + r0) * DDIM);
    #pragma unroll
    for (int t = 0; t < 4; t++) {
        int idx = tid + t * 256;          // float4 index
        int r = idx >> 4, c4 = (idx & 15) << 2;
        float4 v = Ab4[idx];
        sAT[c4 + 0][r] = DNORM * v.x;
        sAT[c4 + 1][r] = DNORM * v.y;
        sAT[c4 + 2][r] = DNORM * v.z;
        sAT[c4 + 3][r] = DNORM * v.w;
    }
    __syncthreads();

    // diag = sum(data^2)*0.5*dn^2 = 0.5*sum(scaled^2)
    if (tid < 64) {
        float s = 0.f;
        #pragma unroll
        for (int c = 0; c < DDIM; c++) { float w = sAT[c][tid]; s = fmaf(w, w, s); }
        g_diag[(size_t)bh * SEQ + r0 + tid] = 0.5f * s;
    }

    float rmax[4] = { -3.4e38f, -3.4e38f, -3.4e38f, -3.4e38f };

    for (int jc = 0; jc < NCH; jc++) {
        const int j0 = jc * 64;
        __syncthreads();
        if (jc < 4) {
            // full chunk: vectorized P fill
            const float4* Pb4 = reinterpret_cast<const float4*>(P + j0 * DDIM);
            #pragma unroll
            for (int t = 0; t < 4; t++) {
                int idx = tid + t * 256;
                int jr = idx >> 4, c4 = (idx & 15) << 2;
                float4 v = Pb4[idx];
                sPT[c4 + 0][jr] = v.x;
                sPT[c4 + 1][jr] = v.y;
                sPT[c4 + 2][jr] = v.z;
                sPT[c4 + 3][jr] = v.w;
            }
        } else {
            #pragma unroll
            for (int t = 0; t < 16; t++) {
                int idx = tid + t * 256;
                int jr = idx >> 6, c = idx & 63;
                int j = j0 + jr;
                sPT[c][jr] = (j < MDIM) ? P[j * DDIM + c] : 0.f;
            }
        }
        __syncthreads();

        float acc[4][4] = {};
        #pragma unroll
        for (int k = 0; k < DDIM; k++) {
            float4 a4 = *reinterpret_cast<const float4*>(&sAT[k][ty * 4]);
            float4 b4 = *reinterpret_cast<const float4*>(&sPT[k][tx * 4]);
            float av[4] = {a4.x, a4.y, a4.z, a4.w};
            float bv[4] = {b4.x, b4.y, b4.z, b4.w};
            #pragma unroll
            for (int r = 0; r < 4; r++)
                #pragma unroll
                for (int j = 0; j < 4; j++)
                    acc[r][j] = fmaf(av[r], bv[j], acc[r][j]);
        }
        #pragma unroll
        for (int r = 0; r < 4; r++) {
            const int row = r0 + ty * 4 + r;
            float* dp = g_dash + ((size_t)bh * SEQ + row) * MDIM;
            if (jc < 4) {
                // full chunk: vector store + max
                float4 o; o.x = acc[r][0]; o.y = acc[r][1]; o.z = acc[r][2]; o.w = acc[r][3];
                // g_dash row base is 266 floats -> not 16B aligned per row; use 2x float2
                *reinterpret_cast<float2*>(dp + j0 + tx * 4)     = make_float2(o.x, o.y);
                *reinterpret_cast<float2*>(dp + j0 + tx * 4 + 2) = make_float2(o.z, o.w);
                rmax[r] = fmaxf(rmax[r], fmaxf(fmaxf(o.x, o.y), fmaxf(o.z, o.w)));
            } else {
                #pragma unroll
                for (int j = 0; j < 4; j++) {
                    int jg = j0 + tx * 4 + j;
                    if (jg < MDIM) {
                        dp[jg] = acc[r][j];
                        rmax[r] = fmaxf(rmax[r], acc[r][j]);
                    }
                }
            }
        }
    }

    #pragma unroll
    for (int r = 0; r < 4; r++) sRM[ty * 4 + r][tx] = rmax[r];
    __syncthreads();

    if (tid < 64) {
        float m = sRM[tid][0];
        #pragma unroll
        for (int x = 1; x < 16; x++) m = fmaxf(m, sRM[tid][x]);
        if (IS_QUERY) {
            g_rowmax[(size_t)bh * SEQ + r0 + tid] = m;   // per-row stabilizer
        } else {
            sRM[tid][16] = m;
        }
    }
    if (!IS_QUERY) {
        __syncthreads();
        if (tid == 0) {
            float m = sRM[0][16];
            for (int r = 1; r < 64; r++) m = fmaxf(m, sRM[r][16]);
            atomicMax(&g_kstab_bits, enc_f(m));          // global stabilizer
        }
    }
}

// ---------------------------------------------------------------------
// context[bh][j][e] = sum_i kp[i][j]*v[i][e] / N ;  col 64 = kmean[j]
// kp computed on the fly from g_dash (kd). block: 64 j-cols x 64 e, K=SEQ
// ---------------------------------------------------------------------
__global__ void __launch_bounds__(256) ctx_kernel(const float* __restrict__ V)
{
    const int bh  = blockIdx.y;
    const int j0  = blockIdx.x * 64;
    const int tid = threadIdx.x;
    const int tx  = tid & 15, ty = tid >> 4;
    const float RATIO = 1.0f / sqrtf(266.0f);
    const float kstab = dec_f(g_kstab_bits);

    __shared__ __align__(16) float sKP[32][68];
    __shared__ __align__(16) float sV[32][68];
    __shared__ float sOff[32];

    float acc[4][4] = {};
    float km = 0.f;
    const float* Vb = V + (size_t)bh * SEQ * DDIM;

    for (int i0 = 0; i0 < SEQ; i0 += 32) {
        __syncthreads();
        if (tid < 32) sOff[tid] = g_diag[(size_t)bh * SEQ + i0 + tid] + kstab;
        __syncthreads();
        #pragma unroll
        for (int t = 0; t < 8; t++) {
            int idx = tid + t * 256;
            int ii = idx >> 6, jj = idx & 63;
            int j = j0 + jj;
            float w = 0.f;
            if (j < MDIM) {
                float kd = g_dash[((size_t)bh * SEQ + i0 + ii) * MDIM + j];
                w = RATIO * (expf(kd - sOff[ii]) + EPSF);
            }
            sKP[ii][jj] = w;
        }
        {
            // vectorized V fill: 32x64 floats = 512 float4
            const float4* Vb4 = reinterpret_cast<const float4*>(
                Vb + (size_t)i0 * DDIM);
            #pragma unroll
            for (int t = 0; t < 2; t++) {
                int idx = tid + t * 256;
                int ii = idx >> 4, e4 = (idx & 15) << 2;
                float4 v = Vb4[idx];
                *reinterpret_cast<float4*>(&sV[ii][e4]) = v;
            }
        }
        __syncthreads();
        #pragma unroll 8
        for (int ii = 0; ii < 32; ii++) {
            float4 a4 = *reinterpret_cast<const float4*>(&sKP[ii][ty * 4]);
            float4 b4 = *reinterpret_cast<const float4*>(&sV[ii][tx * 4]);
            float av[4] = {a4.x, a4.y, a4.z, a4.w};
            float bv[4] = {b4.x, b4.y, b4.z, b4.w};
            #pragma unroll
            for (int r = 0; r < 4; r++)
                #pragma unroll
                for (int e = 0; e < 4; e++)
                    acc[r][e] = fmaf(av[r], bv[e], acc[r][e]);
        }
        if (tid < 64) {
            #pragma unroll
            for (int ii = 0; ii < 32; ii++) km += sKP[ii][tid];
        }
    }

    const float invN = 1.0f / (float)SEQ;
    #pragma unroll
    for (int r = 0; r < 4; r++) {
        int j = j0 + ty * 4 + r;
        if (j < MDIM) {
            float* cp = g_ctx + ((size_t)bh * MDIM + j) * CTXW;
            #pragma unroll
            for (int e = 0; e < 4; e++) cp[tx * 4 + e] = acc[r][e] * invN;
        }
    }
    if (tid < 64) {
        int j = j0 + tid;
        if (j < MDIM) g_ctx[((size_t)bh * MDIM + j) * CTXW + 64] = km * invN;
    }
}

// ---------------------------------------------------------------------
// out[i][e] = (1/den_i) * sum_j qp[i][j]*ctx[j][e];  den_i = sum_j qp*kmean
// qp from g_dash (qd). block: 64 rows of one bh, j in 5 chunks of 64.
// ---------------------------------------------------------------------
__global__ void __launch_bounds__(256) out_kernel(float* __restrict__ Out)
{
    const int bh  = blockIdx.y;
    const int r0  = blockIdx.x * 64;
    const int tid = threadIdx.x;
    const int tx  = tid & 15, ty = tid >> 4;
    const float RATIO = 1.0f / sqrtf(266.0f);

    __shared__ __align__(16) float sQPT[64][68];  // [jj][row] (transposed)
    __shared__ __align__(16) float sCTX[64][68];  // [jj][e]
    __shared__ float sKM[64];
    __shared__ float sOff[64];
    __shared__ float sDinv[64];

    if (tid < 64)
        sOff[tid] = g_diag[(size_t)bh * SEQ + r0 + tid] +
                    g_rowmax[(size_t)bh * SEQ + r0 + tid];

    float acc[4][4] = {};
    float den = 0.f;

    for (int jc = 0; jc < NCH; jc++) {
        const int j0 = jc * 64;
        __syncthreads();
        #pragma unroll
        for (int t = 0; t < 16; t++) {
            int idx = tid + t * 256;
            int r = idx >> 6, jj = idx & 63;
            int j = j0 + jj;
            float w = 0.f;
            if (j < MDIM) {
                float qd = g_dash[((size_t)bh * SEQ + r0 + r) * MDIM + j];
                w = RATIO * (expf(qd - sOff[r]) + EPSF);
            }
            sQPT[jj][r] = w;
        }
        #pragma unroll
        for (int t = 0; t < 16; t++) {
            int idx = tid + t * 256;
            int jj = idx >> 6, e = idx & 63;
            int j = j0 + jj;
            sCTX[jj][e] = (j < MDIM) ? g_ctx[((size_t)bh * MDIM + j) * CTXW + e] : 0.f;
        }
        if (tid < 64) {
            int j = j0 + tid;
            sKM[tid] = (j < MDIM) ? g_ctx[((size_t)bh * MDIM + j) * CTXW + 64] : 0.f;
        }
        __syncthreads();
        #pragma unroll 8
        for (int jj = 0; jj < 64; jj++) {
            float4 a4 = *reinterpret_cast<const float4*>(&sQPT[jj][ty * 4]);
            float4 b4 = *reinterpret_cast<const float4*>(&sCTX[jj][tx * 4]);
            float av[4] = {a4.x, a4.y, a4.z, a4.w};
            float bv[4] = {b4.x, b4.y, b4.z, b4.w};
            #pragma unroll
            for (int r = 0; r < 4; r++)
                #pragma unroll
                for (int e = 0; e < 4; e++)
                    acc[r][e] = fmaf(av[r], bv[e], acc[r][e]);
        }
        if (tid < 64) {
            #pragma unroll
            for (int jj = 0; jj < 64; jj++) den = fmaf(sQPT[jj][tid], sKM[jj], den);
        }
    }

    __syncthreads();
    if (tid < 64) sDinv[tid] = 1.0f / den;
    __syncthreads();

    float* Ob = Out + ((size_t)bh * SEQ + r0) * DDIM;
    #pragma unroll
    for (int r = 0; r < 4; r++) {
        float dv = sDinv[ty * 4 + r];
        #pragma unroll
        for (int e = 0; e < 4; e++)
            Ob[(ty * 4 + r) * DDIM + tx * 4 + e] = dv * acc[r][e];
    }
}

// ---------------------------------------------------------------------
extern "C" void kernel_launch(void* const* d_in, const int* in_sizes, int n_in,
                              void* d_out, int out_size)
{
    const float* q = (const float*)d_in[0];
    const float* k = (const float*)d_in[1];
    const float* v = (const float*)d_in[2];
    const float* P = (const float*)d_in[3];
    float* out = (float*)d_out;

    reset_kernel<<<1, 1>>>();
    dash_kernel<false><<<dim3(SEQ / 64, BHX), 256>>>(k, P);  // kd + global max
    ctx_kernel<<<dim3(NCH, BHX), 256>>>(v);                  // context + kmean
    dash_kernel<true><<<dim3(SEQ / 64, BHX), 256>>>(q, P);   // qd + row max
    out_kernel<<<dim3(SEQ / 64, BHX), 256>>>(out);           // qp@ctx * Dinv
}

// round 8
// speedup vs baseline: 1.4687x; 1.4687x over previous
#include <cuda_runtime.h>
#include <math.h>

// Problem constants (fixed by the benchmark shapes)
#define BHX   32          // b*h = 4*8
#define SEQ   4096        // n
#define DDIM  64          // d (= e)
#define MDIM  266         // m = number of random features
#define NCH   5           // ceil(M/64) column chunks
#define CTXW  65          // context width: 64 v-cols + 1 kmean col
#define KSPL  8           // split-K factor for context GEMM
#define KROWS (SEQ / KSPL) // 512 rows per split
#define EPSF  1e-4f
#define DNORM 0.35355339059327373f   // 64^-0.25
#define CTXTOT (BHX * MDIM * CTXW)   // 553280 (divisible by 4)

// -------- persistent scratch (device globals: allocation-free) --------
__device__ float        g_dash[(size_t)BHX * SEQ * MDIM]; // kd then qd (139.5 MB)
__device__ float        g_diag[BHX * SEQ];
__device__ float        g_rowmax[BHX * SEQ];
__device__ float        g_ctx[CTXTOT];                    // [bh][j][e + kmean]
__device__ float        g_ctx_part[KSPL * CTXTOT];        // split-K partials (17.7 MB)
__device__ unsigned int g_kstab_bits;

// monotonic float <-> uint mapping for deterministic atomicMax on floats
__device__ __forceinline__ unsigned int enc_f(float f) {
    int i = __float_as_int(f);
    return (i >= 0) ? ((unsigned int)i | 0x80000000u) : (unsigned int)(~i);
}
__device__ __forceinline__ float dec_f(unsigned int u) {
    int i = (u & 0x80000000u) ? (int)(u & 0x7fffffffu) : (~(int)u);
    return __int_as_float(i);
}

__global__ void reset_kernel() {
    g_kstab_bits = 0x007FFFFFu;   // enc(-inf)
}

// ---------------------------------------------------------------------
// dash = (DNORM * A) @ P^T    A:[bh][SEQ][64]  P:[266][64]
// also: g_diag (0.5*sum(scaled^2)); row-max (query) or global max (key)
// block: 64 rows of one bh; 256 threads; 4x4 micro-tile
// ---------------------------------------------------------------------
template<bool IS_QUERY>
__global__ void __launch_bounds__(256) dash_kernel(const float* __restrict__ A,
                                                   const float* __restrict__ P)
{
    const int bh  = blockIdx.y;
    const int r0  = blockIdx.x * 64;
    const int tid = threadIdx.x;
    const int tx  = tid & 15, ty = tid >> 4;

    __shared__ __align__(16) float sAT[DDIM][68];  // [k][row]  (transposed)
    __shared__ __align__(16) float sPT[DDIM][68];  // [k][jrel] (transposed)
    __shared__ float sRM[64][17];

    // vectorized fill: 64 rows x 64 cols = 4096 floats = 1024 float4
    const float4* Ab4 = reinterpret_cast<const float4*>(
        A + ((size_t)bh * SEQ + r0) * DDIM);
    #pragma unroll
    for (int t = 0; t < 4; t++) {
        int idx = tid + t * 256;          // float4 index
        int r = idx >> 4, c4 = (idx & 15) << 2;
        float4 v = Ab4[idx];
        sAT[c4 + 0][r] = DNORM * v.x;
        sAT[c4 + 1][r] = DNORM * v.y;
        sAT[c4 + 2][r] = DNORM * v.z;
        sAT[c4 + 3][r] = DNORM * v.w;
    }
    __syncthreads();

    // diag = sum(data^2)*0.5*dn^2 = 0.5*sum(scaled^2)
    if (tid < 64) {
        float s = 0.f;
        #pragma unroll
        for (int c = 0; c < DDIM; c++) { float w = sAT[c][tid]; s = fmaf(w, w, s); }
        g_diag[(size_t)bh * SEQ + r0 + tid] = 0.5f * s;
    }

    float rmax[4] = { -3.4e38f, -3.4e38f, -3.4e38f, -3.4e38f };

    for (int jc = 0; jc < NCH; jc++) {
        const int j0 = jc * 64;
        __syncthreads();
        if (jc < 4) {
            // full chunk: vectorized P fill
            const float4* Pb4 = reinterpret_cast<const float4*>(P + j0 * DDIM);
            #pragma unroll
            for (int t = 0; t < 4; t++) {
                int idx = tid + t * 256;
                int jr = idx >> 4, c4 = (idx & 15) << 2;
                float4 v = Pb4[idx];
                sPT[c4 + 0][jr] = v.x;
                sPT[c4 + 1][jr] = v.y;
                sPT[c4 + 2][jr] = v.z;
                sPT[c4 + 3][jr] = v.w;
            }
        } else {
            #pragma unroll
            for (int t = 0; t < 16; t++) {
                int idx = tid + t * 256;
                int jr = idx >> 6, c = idx & 63;
                int j = j0 + jr;
                sPT[c][jr] = (j < MDIM) ? P[j * DDIM + c] : 0.f;
            }
        }
        __syncthreads();

        float acc[4][4] = {};
        #pragma unroll
        for (int k = 0; k < DDIM; k++) {
            float4 a4 = *reinterpret_cast<const float4*>(&sAT[k][ty * 4]);
            float4 b4 = *reinterpret_cast<const float4*>(&sPT[k][tx * 4]);
            float av[4] = {a4.x, a4.y, a4.z, a4.w};
            float bv[4] = {b4.x, b4.y, b4.z, b4.w};
            #pragma unroll
            for (int r = 0; r < 4; r++)
                #pragma unroll
                for (int j = 0; j < 4; j++)
                    acc[r][j] = fmaf(av[r], bv[j], acc[r][j]);
        }
        #pragma unroll
        for (int r = 0; r < 4; r++) {
            const int row = r0 + ty * 4 + r;
            float* dp = g_dash + ((size_t)bh * SEQ + row) * MDIM;
            if (jc < 4) {
                float4 o; o.x = acc[r][0]; o.y = acc[r][1]; o.z = acc[r][2]; o.w = acc[r][3];
                // g_dash row stride is 266 floats -> rows not 16B-aligned; 2x float2
                *reinterpret_cast<float2*>(dp + j0 + tx * 4)     = make_float2(o.x, o.y);
                *reinterpret_cast<float2*>(dp + j0 + tx * 4 + 2) = make_float2(o.z, o.w);
                rmax[r] = fmaxf(rmax[r], fmaxf(fmaxf(o.x, o.y), fmaxf(o.z, o.w)));
            } else {
                #pragma unroll
                for (int j = 0; j < 4; j++) {
                    int jg = j0 + tx * 4 + j;
                    if (jg < MDIM) {
                        dp[jg] = acc[r][j];
                        rmax[r] = fmaxf(rmax[r], acc[r][j]);
                    }
                }
            }
        }
    }

    #pragma unroll
    for (int r = 0; r < 4; r++) sRM[ty * 4 + r][tx] = rmax[r];
    __syncthreads();

    if (tid < 64) {
        float m = sRM[tid][0];
        #pragma unroll
        for (int x = 1; x < 16; x++) m = fmaxf(m, sRM[tid][x]);
        if (IS_QUERY) {
            g_rowmax[(size_t)bh * SEQ + r0 + tid] = m;   // per-row stabilizer
        } else {
            sRM[tid][16] = m;
        }
    }
    if (!IS_QUERY) {
        __syncthreads();
        if (tid == 0) {
            float m = sRM[0][16];
            for (int r = 1; r < 64; r++) m = fmaxf(m, sRM[r][16]);
            atomicMax(&g_kstab_bits, enc_f(m));          // global stabilizer
        }
    }
}

// ---------------------------------------------------------------------
// ctx partial: part[ks][bh][j][e] = sum_{i in split ks} kp[i][j]*v[i][e]
// col 64 = sum kp[i][j]. kp computed on the fly from g_dash (kd).
// block: 64 j x 64 e, K=KROWS. grid (NCH, KSPL, BHX) = 1280 blocks.
// ---------------------------------------------------------------------
__global__ void __launch_bounds__(256) ctx_kernel(const float* __restrict__ V)
{
    const int bh  = blockIdx.z;
    const int ks  = blockIdx.y;
    const int j0  = blockIdx.x * 64;
    const int tid = threadIdx.x;
    const int tx  = tid & 15, ty = tid >> 4;
    const float RATIO = 1.0f / sqrtf(266.0f);
    const float kstab = dec_f(g_kstab_bits);
    const int rbase = ks * KROWS;

    __shared__ __align__(16) float sKP[32][68];
    __shared__ __align__(16) float sV[32][68];
    __shared__ float sOffAll[KROWS];

    // preload all diag+stab offsets for this split (once)
    #pragma unroll
    for (int t = 0; t < KROWS / 256; t++) {
        int i = tid + t * 256;
        sOffAll[i] = g_diag[(size_t)bh * SEQ + rbase + i] + kstab;
    }

    float acc[4][4] = {};
    float km = 0.f;
    const float* Vb = V + ((size_t)bh * SEQ + rbase) * DDIM;

    for (int i0 = 0; i0 < KROWS; i0 += 32) {
        __syncthreads();
        #pragma unroll
        for (int t = 0; t < 8; t++) {
            int idx = tid + t * 256;
            int ii = idx >> 6, jj = idx & 63;
            int j = j0 + jj;
            float w = 0.f;
            if (j < MDIM) {
                float kd = g_dash[((size_t)bh * SEQ + rbase + i0 + ii) * MDIM + j];
                w = RATIO * (expf(kd - sOffAll[i0 + ii]) + EPSF);
            }
            sKP[ii][jj] = w;
        }
        {
            const float4* Vb4 = reinterpret_cast<const float4*>(Vb + (size_t)i0 * DDIM);
            #pragma unroll
            for (int t = 0; t < 2; t++) {
                int idx = tid + t * 256;
                int ii = idx >> 4, e4 = (idx & 15) << 2;
                *reinterpret_cast<float4*>(&sV[ii][e4]) = Vb4[idx];
            }
        }
        __syncthreads();
        #pragma unroll 8
        for (int ii = 0; ii < 32; ii++) {
            float4 a4 = *reinterpret_cast<const float4*>(&sKP[ii][ty * 4]);
            float4 b4 = *reinterpret_cast<const float4*>(&sV[ii][tx * 4]);
            float av[4] = {a4.x, a4.y, a4.z, a4.w};
            float bv[4] = {b4.x, b4.y, b4.z, b4.w};
            #pragma unroll
            for (int r = 0; r < 4; r++)
                #pragma unroll
                for (int e = 0; e < 4; e++)
                    acc[r][e] = fmaf(av[r], bv[e], acc[r][e]);
        }
        if (tid < 64) {
            #pragma unroll
            for (int ii = 0; ii < 32; ii++) km += sKP[ii][tid];
        }
    }

    float* base = g_ctx_part + (size_t)ks * CTXTOT;
    #pragma unroll
    for (int r = 0; r < 4; r++) {
        int j = j0 + ty * 4 + r;
        if (j < MDIM) {
            float* cp = base + ((size_t)bh * MDIM + j) * CTXW;
            #pragma unroll
            for (int e = 0; e < 4; e++) cp[tx * 4 + e] = acc[r][e];
        }
    }
    if (tid < 64) {
        int j = j0 + tid;
        if (j < MDIM) base[((size_t)bh * MDIM + j) * CTXW + 64] = km;
    }
}

// ---------------------------------------------------------------------
// deterministic split-K reduction: g_ctx = (1/SEQ) * sum_ks partials
// vectorized: CTXTOT % 4 == 0, all bases/strides 16B-aligned
// ---------------------------------------------------------------------
__global__ void __launch_bounds__(256) ctx_reduce_kernel()
{
    const int idx4 = blockIdx.x * 256 + threadIdx.x;   // float4 index
    if (idx4 >= CTXTOT / 4) return;
    const float4* p0 = reinterpret_cast<const float4*>(g_ctx_part) + idx4;
    float4 s = *p0;
    #pragma unroll
    for (int ks = 1; ks < KSPL; ks++) {
        float4 t = *(p0 + (size_t)ks * (CTXTOT / 4));
        s.x += t.x; s.y += t.y; s.z += t.z; s.w += t.w;
    }
    const float invN = 1.0f / (float)SEQ;
    s.x *= invN; s.y *= invN; s.z *= invN; s.w *= invN;
    reinterpret_cast<float4*>(g_ctx)[idx4] = s;
}

// ---------------------------------------------------------------------
// out[i][e] = (1/den_i) * sum_j qp[i][j]*ctx[j][e];  den_i = sum_j qp*kmean
// qp from g_dash (qd). block: 64 rows of one bh, j in 5 chunks of 64.
// ---------------------------------------------------------------------
__global__ void __launch_bounds__(256) out_kernel(float* __restrict__ Out)
{
    const int bh  = blockIdx.y;
    const int r0  = blockIdx.x * 64;
    const int tid = threadIdx.x;
    const int tx  = tid & 15, ty = tid >> 4;
    const float RATIO = 1.0f / sqrtf(266.0f);

    __shared__ __align__(16) float sQPT[64][68];  // [jj][row] (transposed)
    __shared__ __align__(16) float sCTX[64][68];  // [jj][e]
    __shared__ float sKM[64];
    __shared__ float sOff[64];
    __shared__ float sDinv[64];

    if (tid < 64)
        sOff[tid] = g_diag[(size_t)bh * SEQ + r0 + tid] +
                    g_rowmax[(size_t)bh * SEQ + r0 + tid];

    float acc[4][4] = {};
    float den = 0.f;

    for (int jc = 0; jc < NCH; jc++) {
        const int j0 = jc * 64;
        __syncthreads();
        #pragma unroll
        for (int t = 0; t < 16; t++) {
            int idx = tid + t * 256;
            int r = idx >> 6, jj = idx & 63;
            int j = j0 + jj;
            float w = 0.f;
            if (j < MDIM) {
                float qd = g_dash[((size_t)bh * SEQ + r0 + r) * MDIM + j];
                w = RATIO * (expf(qd - sOff[r]) + EPSF);
            }
            sQPT[jj][r] = w;
        }
        #pragma unroll
        for (int t = 0; t < 16; t++) {
            int idx = tid + t * 256;
            int jj = idx >> 6, e = idx & 63;
            int j = j0 + jj;
            sCTX[jj][e] = (j < MDIM) ? g_ctx[((size_t)bh * MDIM + j) * CTXW + e] : 0.f;
        }
        if (tid < 64) {
            int j = j0 + tid;
            sKM[tid] = (j < MDIM) ? g_ctx[((size_t)bh * MDIM + j) * CTXW + 64] : 0.f;
        }
        __syncthreads();
        #pragma unroll 8
        for (int jj = 0; jj < 64; jj++) {
            float4 a4 = *reinterpret_cast<const float4*>(&sQPT[jj][ty * 4]);
            float4 b4 = *reinterpret_cast<const float4*>(&sCTX[jj][tx * 4]);
            float av[4] = {a4.x, a4.y, a4.z, a4.w};
            float bv[4] = {b4.x, b4.y, b4.z, b4.w};
            #pragma unroll
            for (int r = 0; r < 4; r++)
                #pragma unroll
                for (int e = 0; e < 4; e++)
                    acc[r][e] = fmaf(av[r], bv[e], acc[r][e]);
        }
        if (tid < 64) {
            #pragma unroll
            for (int jj = 0; jj < 64; jj++) den = fmaf(sQPT[jj][tid], sKM[jj], den);
        }
    }

    __syncthreads();
    if (tid < 64) sDinv[tid] = 1.0f / den;
    __syncthreads();

    float* Ob = Out + ((size_t)bh * SEQ + r0) * DDIM;
    #pragma unroll
    for (int r = 0; r < 4; r++) {
        float dv = sDinv[ty * 4 + r];
        #pragma unroll
        for (int e = 0; e < 4; e++)
            Ob[(ty * 4 + r) * DDIM + tx * 4 + e] = dv * acc[r][e];
    }
}

// ---------------------------------------------------------------------
extern "C" void kernel_launch(void* const* d_in, const int* in_sizes, int n_in,
                              void* d_out, int out_size)
{
    const float* q = (const float*)d_in[0];
    const float* k = (const float*)d_in[1];
    const float* v = (const float*)d_in[2];
    const float* P = (const float*)d_in[3];
    float* out = (float*)d_out;

    reset_kernel<<<1, 1>>>();
    dash_kernel<false><<<dim3(SEQ / 64, BHX), 256>>>(k, P);   // kd + global max
    ctx_kernel<<<dim3(NCH, KSPL, BHX), 256>>>(v);             // split-K partials
    ctx_reduce_kernel<<<(CTXTOT / 4 + 255) / 256, 256>>>();   // + kmean, /N
    dash_kernel<true><<<dim3(SEQ / 64, BHX), 256>>>(q, P);    // qd + row max
    out_kernel<<<dim3(SEQ / 64, BHX), 256>>>(out);            // qp@ctx * Dinv
}

// round 16
// speedup vs baseline: 1.6857x; 1.1478x over previous
#include <cuda_runtime.h>
#include <cuda_bf16.h>
#include <math.h>
#include <stdint.h>

// Problem constants
#define BHX   32
#define SEQ   4096
#define DDIM  64
#define MDIM  266
#define NCH   5            // 64-wide chunks for ctx/out
#define NTIL  34           // 8-wide N-tiles for dash_mma (272 >= 266)
#define PPAD  288
#define CTXW  65
#define KSPL  8
#define KROWS (SEQ / KSPL)
#define EPSF  1e-4f
#define DNORM 0.35355339059327373f
#define CTXTOT (BHX * MDIM * CTXW)

// -------- persistent scratch (device globals: allocation-free) --------
__device__ float        g_dash[(size_t)BHX * SEQ * MDIM];
__device__ float        g_diag_k[BHX * SEQ];
__device__ float        g_diag_q[BHX * SEQ];
__device__ float        g_rowmax[BHX * SEQ];
__device__ float        g_ctx[CTXTOT];
__device__ float        g_ctx_part[KSPL * CTXTOT];
__device__ unsigned int g_kstab_bits;
// bf16 hi/lo decompositions, packed 2 bf16 per word (32 words per 64-col row)
__device__ uint4        g_khi4[(size_t)BHX * SEQ * 8];
__device__ uint4        g_klo4[(size_t)BHX * SEQ * 8];
__device__ uint4        g_qhi4[(size_t)BHX * SEQ * 8];
__device__ uint4        g_qlo4[(size_t)BHX * SEQ * 8];
__device__ uint4        g_phi4[PPAD * 8];
__device__ uint4        g_plo4[PPAD * 8];

__device__ __forceinline__ unsigned int enc_f(float f) {
    int i = __float_as_int(f);
    return (i >= 0) ? ((unsigned int)i | 0x80000000u) : (unsigned int)(~i);
}
__device__ __forceinline__ float dec_f(unsigned int u) {
    int i = (u & 0x80000000u) ? (int)(u & 0x7fffffffu) : (~(int)u);
    return __int_as_float(i);
}

__global__ void reset_kernel() { g_kstab_bits = 0x007FFFFFu; }

// m16n8k16 bf16 MMA, fp32 accumulate (sm_80+ PTX; no sm_103a-gated features)
__device__ __forceinline__ void mma16816(float* d, const uint32_t* a, const uint32_t* b) {
    asm volatile(
        "mma.sync.aligned.m16n8k16.row.col.f32.bf16.bf16.f32 "
        "{%0,%1,%2,%3}, {%4,%5,%6,%7}, {%8,%9}, {%0,%1,%2,%3};"
        : "+f"(d[0]), "+f"(d[1]), "+f"(d[2]), "+f"(d[3])
        : "r"(a[0]), "r"(a[1]), "r"(a[2]), "r"(a[3]), "r"(b[0]), "r"(b[1]));
}

// ---------------------------------------------------------------------
// prep: hi/lo bf16 decomposition of DNORM*A + per-row diag (warp per row)
// ---------------------------------------------------------------------
template<bool IS_QUERY>
__global__ void __launch_bounds__(256) prep_qk(const float* __restrict__ src)
{
    const int warp = threadIdx.x >> 5, lane = threadIdx.x & 31;
    const size_t row = (size_t)blockIdx.x * 8 + warp;   // < BHX*SEQ
    const float2 v = reinterpret_cast<const float2*>(src)[row * 32 + lane];
    float s1 = DNORM * v.x, s2 = DNORM * v.y;
    __nv_bfloat16 h1 = __float2bfloat16(s1);
    __nv_bfloat16 h2 = __float2bfloat16(s2);
    __nv_bfloat16 l1 = __float2bfloat16(s1 - __bfloat162float(h1));
    __nv_bfloat16 l2 = __float2bfloat16(s2 - __bfloat162float(h2));
    unsigned int* dhi = reinterpret_cast<unsigned int*>(IS_QUERY ? g_qhi4 : g_khi4);
    unsigned int* dlo = reinterpret_cast<unsigned int*>(IS_QUERY ? g_qlo4 : g_klo4);
    dhi[row * 32 + lane] = ((uint32_t)__bfloat16_as_ushort(h2) << 16) | __bfloat16_as_ushort(h1);
    dlo[row * 32 + lane] = ((uint32_t)__bfloat16_as_ushort(l2) << 16) | __bfloat16_as_ushort(l1);
    float d = fmaf(s1, s1, s2 * s2);
    #pragma unroll
    for (int o = 16; o; o >>= 1) d += __shfl_xor_sync(0xFFFFFFFFu, d, o);
    if (lane == 0) {
        if (IS_QUERY) g_diag_q[row] = 0.5f * d; else g_diag_k[row] = 0.5f * d;
    }
}

__global__ void __launch_bounds__(256) prep_p(const float* __restrict__ P)
{
    const int warp = threadIdx.x >> 5, lane = threadIdx.x & 31;
    const int row = blockIdx.x * 8 + warp;              // < PPAD
    float s1 = 0.f, s2 = 0.f;
    if (row < MDIM) {
        float2 v = reinterpret_cast<const float2*>(P)[(size_t)row * 32 + lane];
        s1 = v.x; s2 = v.y;
    }
    __nv_bfloat16 h1 = __float2bfloat16(s1);
    __nv_bfloat16 h2 = __float2bfloat16(s2);
    __nv_bfloat16 l1 = __float2bfloat16(s1 - __bfloat162float(h1));
    __nv_bfloat16 l2 = __float2bfloat16(s2 - __bfloat162float(h2));
    reinterpret_cast<unsigned int*>(g_phi4)[row * 32 + lane] =
        ((uint32_t)__bfloat16_as_ushort(h2) << 16) | __bfloat16_as_ushort(h1);
    reinterpret_cast<unsigned int*>(g_plo4)[row * 32 + lane] =
        ((uint32_t)__bfloat16_as_ushort(l2) << 16) | __bfloat16_as_ushort(l1);
}

// ---------------------------------------------------------------------
// dash_mma: warp-level split-bf16 mma.sync GEMM.
// Warp owns 16 rows; block = 8 warps = 128 rows. D = A @ P^T.
// m16n8k16 fragments loaded directly from packed hi/lo words:
//   A row-major: a0=(gid, k=2*tig,+1), a1=(gid+8,..), a2/a3 = +8 in k
//   B col-major: b0=(k=2*tig,+1, n=gid), b1 = +8 in k  -> P[j][k] pairs
// 3 split products per k-step (hi*hi, hi*lo, lo*hi), fp32 accum, fixed order.
// ---------------------------------------------------------------------
template<bool IS_QUERY>
__global__ void __launch_bounds__(256) dash_mma()
{
    const int bh = blockIdx.y, r0 = blockIdx.x * 128;
    const int tid = threadIdx.x, warp = tid >> 5, lane = tid & 31;
    const int gid = lane >> 2, tig = lane & 3;

    const unsigned int* Ahi = reinterpret_cast<const unsigned int*>(IS_QUERY ? g_qhi4 : g_khi4)
                              + ((size_t)bh * SEQ + r0 + warp * 16) * 32;
    const unsigned int* Alo = reinterpret_cast<const unsigned int*>(IS_QUERY ? g_qlo4 : g_klo4)
                              + ((size_t)bh * SEQ + r0 + warp * 16) * 32;
    const unsigned int* Phi = reinterpret_cast<const unsigned int*>(g_phi4);
    const unsigned int* Plo = reinterpret_cast<const unsigned int*>(g_plo4);

    // Load A fragments for all 4 k-steps (k base = ks*16; word idx = ks*8 + tig [+4 for k+8])
    uint32_t ahi[16], alo[16];
    #pragma unroll
    for (int ks = 0; ks < 4; ks++) {
        int w = ks * 8 + tig;
        ahi[ks*4+0] = Ahi[gid * 32 + w];        alo[ks*4+0] = Alo[gid * 32 + w];
        ahi[ks*4+1] = Ahi[(gid+8) * 32 + w];    alo[ks*4+1] = Alo[(gid+8) * 32 + w];
        ahi[ks*4+2] = Ahi[gid * 32 + w + 4];    alo[ks*4+2] = Alo[gid * 32 + w + 4];
        ahi[ks*4+3] = Ahi[(gid+8) * 32 + w + 4];alo[ks*4+3] = Alo[(gid+8) * 32 + w + 4];
    }

    const size_t row_g  = (size_t)bh * SEQ + r0 + warp * 16 + gid;
    float* dp0 = g_dash + row_g * MDIM;
    float* dp1 = g_dash + (row_g + 8) * MDIM;
    float rm0 = -3.4e38f, rm1 = -3.4e38f;

    for (int nt = 0; nt < NTIL; nt++) {
        const int j = nt * 8 + gid;          // < 272 <= PPAD (zero-padded), no guard
        float d[4] = {0.f, 0.f, 0.f, 0.f};
        #pragma unroll
        for (int ks = 0; ks < 4; ks++) {
            int w = j * 32 + ks * 8 + tig;
            uint32_t bhi[2] = { Phi[w], Phi[w + 4] };
            uint32_t blo[2] = { Plo[w], Plo[w + 4] };
            mma16816(d, &ahi[ks*4], bhi);
            mma16816(d, &ahi[ks*4], blo);
            mma16816(d, &alo[ks*4], bhi);
        }
        const int c0 = nt * 8 + tig * 2;     // this thread's column pair
        if (c0 + 1 < MDIM + 1 && c0 < MDIM) {  // pair fully valid iff c0+1 < 266; c0 even, MDIM even -> c0<266 implies pair valid
            *reinterpret_cast<float2*>(dp0 + c0) = make_float2(d[0], d[1]);
            *reinterpret_cast<float2*>(dp1 + c0) = make_float2(d[2], d[3]);
            rm0 = fmaxf(rm0, fmaxf(d[0], d[1]));
            rm1 = fmaxf(rm1, fmaxf(d[2], d[3]));
        }
    }

    // reduce row max over the 4 lanes sharing a row (tig dimension: xor 1, 2)
    rm0 = fmaxf(rm0, __shfl_xor_sync(0xFFFFFFFFu, rm0, 1));
    rm0 = fmaxf(rm0, __shfl_xor_sync(0xFFFFFFFFu, rm0, 2));
    rm1 = fmaxf(rm1, __shfl_xor_sync(0xFFFFFFFFu, rm1, 1));
    rm1 = fmaxf(rm1, __shfl_xor_sync(0xFFFFFFFFu, rm1, 2));

    if (IS_QUERY) {
        if (tig == 0) {
            g_rowmax[row_g]     = rm0;
            g_rowmax[row_g + 8] = rm1;
        }
    } else {
        __shared__ float red[8];
        float wm = fmaxf(rm0, rm1);
        #pragma unroll
        for (int o = 16; o; o >>= 1) wm = fmaxf(wm, __shfl_xor_sync(0xFFFFFFFFu, wm, o));
        if (lane == 0) red[warp] = wm;
        __syncthreads();
        if (tid == 0) {
            float m = red[0];
            #pragma unroll
            for (int w = 1; w < 8; w++) m = fmaxf(m, red[w]);
            atomicMax(&g_kstab_bits, enc_f(m));
        }
    }
}

// ---------------------------------------------------------------------
// ctx partial (split-K; __expf) — unchanged passing structure
// ---------------------------------------------------------------------
__global__ void __launch_bounds__(256) ctx_kernel(const float* __restrict__ V)
{
    const int bh  = blockIdx.z;
    const int ks  = blockIdx.y;
    const int j0  = blockIdx.x * 64;
    const int tid = threadIdx.x;
    const int tx  = tid & 15, ty = tid >> 4;
    const float RATIO = 1.0f / sqrtf(266.0f);
    const float kstab = dec_f(g_kstab_bits);
    const int rbase = ks * KROWS;

    __shared__ __align__(16) float sKP[32][68];
    __shared__ __align__(16) float sV[32][68];
    __shared__ float sOffAll[KROWS];

    #pragma unroll
    for (int t = 0; t < KROWS / 256; t++) {
        int i = tid + t * 256;
        sOffAll[i] = g_diag_k[(size_t)bh * SEQ + rbase + i] + kstab;
    }

    float acc[4][4] = {};
    float km = 0.f;
    const float* Vb = V + ((size_t)bh * SEQ + rbase) * DDIM;

    for (int i0 = 0; i0 < KROWS; i0 += 32) {
        __syncthreads();
        #pragma unroll
        for (int t = 0; t < 8; t++) {
            int idx = tid + t * 256;
            int ii = idx >> 6, jj = idx & 63;
            int j = j0 + jj;
            float w = 0.f;
            if (j < MDIM) {
                float kd = g_dash[((size_t)bh * SEQ + rbase + i0 + ii) * MDIM + j];
                w = RATIO * (__expf(kd - sOffAll[i0 + ii]) + EPSF);
            }
            sKP[ii][jj] = w;
        }
        {
            const float4* Vb4 = reinterpret_cast<const float4*>(Vb + (size_t)i0 * DDIM);
            #pragma unroll
            for (int t = 0; t < 2; t++) {
                int idx = tid + t * 256;
                int ii = idx >> 4, e4 = (idx & 15) << 2;
                *reinterpret_cast<float4*>(&sV[ii][e4]) = Vb4[idx];
            }
        }
        __syncthreads();
        #pragma unroll 8
        for (int ii = 0; ii < 32; ii++) {
            float4 a4 = *reinterpret_cast<const float4*>(&sKP[ii][ty * 4]);
            float4 b4 = *reinterpret_cast<const float4*>(&sV[ii][tx * 4]);
            float av[4] = {a4.x, a4.y, a4.z, a4.w};
            float bv[4] = {b4.x, b4.y, b4.z, b4.w};
            #pragma unroll
            for (int r = 0; r < 4; r++)
                #pragma unroll
                for (int e = 0; e < 4; e++)
                    acc[r][e] = fmaf(av[r], bv[e], acc[r][e]);
        }
        if (tid < 64) {
            #pragma unroll
            for (int ii = 0; ii < 32; ii++) km += sKP[ii][tid];
        }
    }

    float* base = g_ctx_part + (size_t)ks * CTXTOT;
    #pragma unroll
    for (int r = 0; r < 4; r++) {
        int j = j0 + ty * 4 + r;
        if (j < MDIM) {
            float* cp = base + ((size_t)bh * MDIM + j) * CTXW;
            #pragma unroll
            for (int e = 0; e < 4; e++) cp[tx * 4 + e] = acc[r][e];
        }
    }
    if (tid < 64) {
        int j = j0 + tid;
        if (j < MDIM) base[((size_t)bh * MDIM + j) * CTXW + 64] = km;
    }
}

__global__ void __launch_bounds__(256) ctx_reduce_kernel()
{
    const int idx4 = blockIdx.x * 256 + threadIdx.x;
    if (idx4 >= CTXTOT / 4) return;
    const float4* p0 = reinterpret_cast<const float4*>(g_ctx_part) + idx4;
    float4 s = *p0;
    #pragma unroll
    for (int ks = 1; ks < KSPL; ks++) {
        float4 t = *(p0 + (size_t)ks * (CTXTOT / 4));
        s.x += t.x; s.y += t.y; s.z += t.z; s.w += t.w;
    }
    const float invN = 1.0f / (float)SEQ;
    s.x *= invN; s.y *= invN; s.z *= invN; s.w *= invN;
    reinterpret_cast<float4*>(g_ctx)[idx4] = s;
}

// ---------------------------------------------------------------------
// out (g_diag_q; __expf) — unchanged passing structure
// ---------------------------------------------------------------------
__global__ void __launch_bounds__(256) out_kernel(float* __restrict__ Out)
{
    const int bh  = blockIdx.y;
    const int r0  = blockIdx.x * 64;
    const int tid = threadIdx.x;
    const int tx  = tid & 15, ty = tid >> 4;
    const float RATIO = 1.0f / sqrtf(266.0f);

    __shared__ __align__(16) float sQPT[64][68];
    __shared__ __align__(16) float sCTX[64][68];
    __shared__ float sKM[64];
    __shared__ float sOff[64];
    __shared__ float sDinv[64];

    if (tid < 64)
        sOff[tid] = g_diag_q[(size_t)bh * SEQ + r0 + tid] +
                    g_rowmax[(size_t)bh * SEQ + r0 + tid];

    float acc[4][4] = {};
    float den = 0.f;

    for (int jc = 0; jc < NCH; jc++) {
        const int j0 = jc * 64;
        __syncthreads();
        #pragma unroll
        for (int t = 0; t < 16; t++) {
            int idx = tid + t * 256;
            int r = idx >> 6, jj = idx & 63;
            int j = j0 + jj;
            float w = 0.f;
            if (j < MDIM) {
                float qd = g_dash[((size_t)bh * SEQ + r0 + r) * MDIM + j];
                w = RATIO * (__expf(qd - sOff[r]) + EPSF);
            }
            sQPT[jj][r] = w;
        }
        #pragma unroll
        for (int t = 0; t < 16; t++) {
            int idx = tid + t * 256;
            int jj = idx >> 6, e = idx & 63;
            int j = j0 + jj;
            sCTX[jj][e] = (j < MDIM) ? g_ctx[((size_t)bh * MDIM + j) * CTXW + e] : 0.f;
        }
        if (tid < 64) {
            int j = j0 + tid;
            sKM[tid] = (j < MDIM) ? g_ctx[((size_t)bh * MDIM + j) * CTXW + 64] : 0.f;
        }
        __syncthreads();
        #pragma unroll 8
        for (int jj = 0; jj < 64; jj++) {
            float4 a4 = *reinterpret_cast<const float4*>(&sQPT[jj][ty * 4]);
            float4 b4 = *reinterpret_cast<const float4*>(&sCTX[jj][tx * 4]);
            float av[4] = {a4.x, a4.y, a4.z, a4.w};
            float bv[4] = {b4.x, b4.y, b4.z, b4.w};
            #pragma unroll
            for (int r = 0; r < 4; r++)
                #pragma unroll
                for (int e = 0; e < 4; e++)
                    acc[r][e] = fmaf(av[r], bv[e], acc[r][e]);
        }
        if (tid < 64) {
            #pragma unroll
            for (int jj = 0; jj < 64; jj++) den = fmaf(sQPT[jj][tid], sKM[jj], den);
        }
    }

    __syncthreads();
    if (tid < 64) sDinv[tid] = 1.0f / den;
    __syncthreads();

    float* Ob = Out + ((size_t)bh * SEQ + r0) * DDIM;
    #pragma unroll
    for (int r = 0; r < 4; r++) {
        float dv = sDinv[ty * 4 + r];
        #pragma unroll
        for (int e = 0; e < 4; e++)
            Ob[(ty * 4 + r) * DDIM + tx * 4 + e] = dv * acc[r][e];
    }
}

// ---------------------------------------------------------------------
extern "C" void kernel_launch(void* const* d_in, const int* in_sizes, int n_in,
                              void* d_out, int out_size)
{
    const float* q = (const float*)d_in[0];
    const float* k = (const float*)d_in[1];
    const float* v = (const float*)d_in[2];
    const float* P = (const float*)d_in[3];
    float* out = (float*)d_out;

    reset_kernel<<<1, 1>>>();
    prep_p<<<PPAD / 8, 256>>>(P);
    prep_qk<false><<<BHX * SEQ / 8, 256>>>(k);
    prep_qk<true><<<BHX * SEQ / 8, 256>>>(q);
    dash_mma<false><<<dim3(SEQ / 128, BHX), 256>>>();         // kd + global max
    ctx_kernel<<<dim3(NCH, KSPL, BHX), 256>>>(v);             // split-K partials
    ctx_reduce_kernel<<<(CTXTOT / 4 + 255) / 256, 256>>>();
    dash_mma<true><<<dim3(SEQ / 128, BHX), 256>>>();          // qd + row max
    out_kernel<<<dim3(SEQ / 64, BHX), 256>>>(out);            // qp@ctx * Dinv
}